// round 4
// baseline (speedup 1.0000x reference)
#include <cuda_runtime.h>
#include <cuda_fp16.h>
#include <cstdint>

// ---------------------------------------------------------------------------
// BitLinear: out = x @ ternary(w)^T + bias
// x: [8192,4096] f32, w: [4096,4096] f32, bias: [4096] f32, out f32.
//
// fp16 mma.sync measured pipe-bound at 280 TF/s (256 FLOP/cyc/SMSP). Switch to
// int8 IMMA m16n8k32 with an exact hi/lo split of x:
//   x = s * (h + l/128),  h,l int8, w ternary int8 (exact), int32 accumulate.
// Reconstruction error <= s/256 -> rel err ~7e-5. Two IMMA chains share B.
// ---------------------------------------------------------------------------

#define MDIM 8192
#define NDIM 4096
#define KDIM 4096

#define BM 128
#define BN 64
#define BK 128
#define KT (KDIM / BK)   // 32

// Scratch (device globals: allocation-free per harness rules)
__device__ double   g_partials[1024];
__device__ unsigned g_count = 0;
__device__ float    g_gamma_inv;
__device__ float    g_xs[MDIM];
__device__ __align__(128) int8_t g_xhi[(size_t)MDIM * KDIM];  // 32 MB
__device__ __align__(128) int8_t g_xlo[(size_t)MDIM * KDIM];  // 32 MB
__device__ __align__(128) int8_t g_wq [(size_t)NDIM * KDIM];  // 16 MB

// ---------------------------------------------------------------------------
// Helpers
// ---------------------------------------------------------------------------
static __device__ __forceinline__ uint32_t smem_u32(const void* p) {
    uint32_t a;
    asm("{ .reg .u64 t; cvta.to.shared.u64 t, %1; cvt.u32.u64 %0, t; }"
        : "=r"(a) : "l"(p));
    return a;
}

static __device__ __forceinline__ void cp_async16(uint32_t s, const void* g) {
    asm volatile("cp.async.cg.shared.global [%0], [%1], 16;" :: "r"(s), "l"(g));
}

// SW128 xor swizzle on byte offsets within 128B rows
#define SWZ(o) ((o) ^ (((o) >> 3) & 0x70))

#define LDSM_X4(r0, r1, r2, r3, addr)                                          \
    asm volatile("ldmatrix.sync.aligned.m8n8.x4.shared.b16 {%0,%1,%2,%3}, [%4];"\
                 : "=r"(r0), "=r"(r1), "=r"(r2), "=r"(r3) : "r"(addr))

#define IMMA_16832(c, a, b)                                                    \
    asm volatile(                                                              \
        "mma.sync.aligned.m16n8k32.row.col.s32.s8.s8.s32 "                     \
        "{%0,%1,%2,%3}, {%4,%5,%6,%7}, {%8,%9}, {%0,%1,%2,%3};"                \
        : "+r"((c)[0]), "+r"((c)[1]), "+r"((c)[2]), "+r"((c)[3])               \
        : "r"((a)[0]), "r"((a)[1]), "r"((a)[2]), "r"((a)[3]),                  \
          "r"((b)[0]), "r"((b)[1]))

// ---------------------------------------------------------------------------
// Launch 1: |w| mean -> g_gamma_inv (grid-wide, last-block finalize)
// ---------------------------------------------------------------------------
__global__ void reduce_gamma_kernel(const float* __restrict__ w) {
    __shared__ double sred[256];
    __shared__ bool is_last;
    const float4* w4 = reinterpret_cast<const float4*>(w);
    const int n4 = (NDIM * KDIM) / 4;
    double s = 0.0;
    for (int i = blockIdx.x * blockDim.x + threadIdx.x; i < n4;
         i += gridDim.x * blockDim.x) {
        float4 v = w4[i];
        s += (double)(fabsf(v.x) + fabsf(v.y) + fabsf(v.z) + fabsf(v.w));
    }
    sred[threadIdx.x] = s;
    __syncthreads();
    for (int o = 128; o > 0; o >>= 1) {
        if (threadIdx.x < o) sred[threadIdx.x] += sred[threadIdx.x + o];
        __syncthreads();
    }
    if (threadIdx.x == 0) {
        g_partials[blockIdx.x] = sred[0];
        __threadfence();
        unsigned c = atomicAdd(&g_count, 1u);
        is_last = (c == gridDim.x - 1);
    }
    __syncthreads();
    if (is_last) {
        double t = 0.0;
        for (int i = threadIdx.x; i < 1024; i += 256) t += __ldcg(&g_partials[i]);
        sred[threadIdx.x] = t;
        __syncthreads();
        for (int o = 128; o > 0; o >>= 1) {
            if (threadIdx.x < o) sred[threadIdx.x] += sred[threadIdx.x + o];
            __syncthreads();
        }
        if (threadIdx.x == 0) {
            double g = sred[0] / (double)((size_t)NDIM * KDIM);
            if (g < 1e-8) g = 1e-8;
            g_gamma_inv = (float)(1.0 / g);
            g_count = 0;   // reset for next graph replay
        }
    }
}

// ---------------------------------------------------------------------------
// Launch 2: fused quantization.
// Blocks [0, MDIM): per-token x -> (hi, lo) int8 + scale.
// Blocks [MDIM, MDIM+4096): w -> ternary int8 (4096 elems per block).
// ---------------------------------------------------------------------------
__global__ void quant_fused_kernel(const float* __restrict__ x,
                                   const float* __restrict__ w) {
    const int bid = blockIdx.x;
    const int tid = threadIdx.x;
    if (bid < MDIM) {
        const float4* xr = reinterpret_cast<const float4*>(x + (size_t)bid * KDIM);
        float4 v[4];
        float mx = 0.f;
        #pragma unroll
        for (int i = 0; i < 4; i++) {
            v[i] = xr[tid + i * 256];
            mx = fmaxf(mx, fmaxf(fmaxf(fabsf(v[i].x), fabsf(v[i].y)),
                                 fmaxf(fabsf(v[i].z), fabsf(v[i].w))));
        }
        __shared__ float smax[256];
        smax[tid] = mx;
        __syncthreads();
        for (int o = 128; o > 0; o >>= 1) {
            if (tid < o) smax[tid] = fmaxf(smax[tid], smax[tid + o]);
            __syncthreads();
        }
        const float s = fmaxf(smax[0], 1e-20f) * (1.0f / 127.0f);
        const float inv_s = 1.0f / s;
        if (tid == 0) g_xs[bid] = s;
        uint32_t* hi = reinterpret_cast<uint32_t*>(g_xhi + (size_t)bid * KDIM);
        uint32_t* lo = reinterpret_cast<uint32_t*>(g_xlo + (size_t)bid * KDIM);
        #pragma unroll
        for (int i = 0; i < 4; i++) {
            const float f[4] = {v[i].x, v[i].y, v[i].z, v[i].w};
            uint32_t hp = 0, lp = 0;
            #pragma unroll
            for (int j = 0; j < 4; j++) {
                float xs = f[j] * inv_s;
                float h = rintf(xs);
                int hq = (int)h;
                int lq = (int)rintf((xs - h) * 128.0f);
                hp |= (uint32_t)(hq & 0xFF) << (j * 8);
                lp |= (uint32_t)(lq & 0xFF) << (j * 8);
            }
            hi[tid + i * 256] = hp;
            lo[tid + i * 256] = lp;
        }
    } else {
        const int wb = bid - MDIM;
        const float ginv = g_gamma_inv;
        const float4* w4 = reinterpret_cast<const float4*>(w) + (size_t)wb * 1024;
        uint32_t* q = reinterpret_cast<uint32_t*>(g_wq) + (size_t)wb * 1024;
        #pragma unroll
        for (int i = 0; i < 4; i++) {
            float4 vv = w4[tid + i * 256];
            int a = (int)fminf(1.f, fmaxf(-1.f, rintf(vv.x * ginv)));
            int b = (int)fminf(1.f, fmaxf(-1.f, rintf(vv.y * ginv)));
            int c = (int)fminf(1.f, fmaxf(-1.f, rintf(vv.z * ginv)));
            int d = (int)fminf(1.f, fmaxf(-1.f, rintf(vv.w * ginv)));
            q[tid + i * 256] = (uint32_t)(a & 0xFF) | ((uint32_t)(b & 0xFF) << 8) |
                               ((uint32_t)(c & 0xFF) << 16) | ((uint32_t)(d & 0xFF) << 24);
        }
    }
}

// ---------------------------------------------------------------------------
// Launch 3: GEMM. CTA tile 128(M) x 64(N), BK=128 int8, 2-stage cp.async.
// Per stage: Ahi 16K | Alo 16K | B 8K = 40960 B. 8 warps: wm=wid&3 (32 rows),
// wn=wid>>2 (32 cols). Per warp: 2 i-tiles x 4 j-tiles, dual IMMA chains.
// ---------------------------------------------------------------------------
static constexpr int STAGE_BYTES = BM * BK + BM * BK + BN * BK;  // 40960
static constexpr int SMEM_BYTES  = 2 * STAGE_BYTES;              // 81920

__global__ __launch_bounds__(256, 2)
void bitlinear_gemm_kernel(const float* __restrict__ bias, float* __restrict__ out) {
    extern __shared__ __align__(128) char smem_raw[];
    const uint32_t sbase = smem_u32(smem_raw);

    const int tid  = threadIdx.x;
    const int wid  = tid >> 5;
    const int lane = tid & 31;
    const int wm = wid & 3;        // 0..3 -> 32 rows each
    const int wn = wid >> 2;       // 0..1 -> 32 cols each
    const int m0 = blockIdx.y * BM;
    const int n0 = blockIdx.x * BN;

    const int8_t* Ah = g_xhi + (size_t)m0 * KDIM;
    const int8_t* Al = g_xlo + (size_t)m0 * KDIM;
    const int8_t* Bw = g_wq  + (size_t)n0 * KDIM;

    const int lrow = tid >> 3;     // 0..31
    const int lkc  = tid & 7;      // 16B chunk within 128B row

    int acc_h[2][4][4], acc_l[2][4][4];
    #pragma unroll
    for (int i = 0; i < 2; i++)
        #pragma unroll
        for (int j = 0; j < 4; j++)
            #pragma unroll
            for (int r = 0; r < 4; r++) { acc_h[i][j][r] = 0; acc_l[i][j][r] = 0; }

    auto load_stage = [&](int kt) {
        const int st = kt & 1;
        const uint32_t sAh = sbase + st * STAGE_BYTES;
        const uint32_t sAl = sAh + BM * BK;
        const uint32_t sB  = sAl + BM * BK;
        const int8_t* ah = Ah + kt * BK;
        const int8_t* al = Al + kt * BK;
        const int8_t* bw = Bw + kt * BK;
        #pragma unroll
        for (int i = 0; i < 4; i++) {
            const int r = lrow + i * 32;
            const uint32_t d = SWZ((uint32_t)(r * 128 + lkc * 16));
            cp_async16(sAh + d, ah + (size_t)r * KDIM + lkc * 16);
            cp_async16(sAl + d, al + (size_t)r * KDIM + lkc * 16);
        }
        #pragma unroll
        for (int i = 0; i < 2; i++) {
            const int r = lrow + i * 32;
            const uint32_t d = SWZ((uint32_t)(r * 128 + lkc * 16));
            cp_async16(sB + d, bw + (size_t)r * KDIM + lkc * 16);
        }
    };

    load_stage(0);
    asm volatile("cp.async.commit_group;" ::: "memory");

    // ldmatrix lane addressing
    const int a_r  = lane & 15;                          // row within m16 tile
    const int a_kb = (lane >> 4) * 16;                   // k-byte half (0/16)
    const int b_n  = ((lane >> 4) & 1) * 8 + (lane & 7); // n within n16 pair
    const int b_kb = ((lane >> 3) & 1) * 16;             // k-byte half

    for (int kt = 0; kt < KT; ++kt) {
        if (kt + 1 < KT) {
            load_stage(kt + 1);
            asm volatile("cp.async.commit_group;" ::: "memory");
            asm volatile("cp.async.wait_group 1;" ::: "memory");
        } else {
            asm volatile("cp.async.wait_group 0;" ::: "memory");
        }
        __syncthreads();

        const int st = kt & 1;
        const uint32_t sAh = sbase + st * STAGE_BYTES;
        const uint32_t sAl = sAh + BM * BK;
        const uint32_t sB  = sAl + BM * BK;

        #pragma unroll
        for (int kk = 0; kk < 4; ++kk) {
            uint32_t ah[2][4], al[2][4];
            #pragma unroll
            for (int i = 0; i < 2; i++) {
                const uint32_t off = (uint32_t)((wm * 32 + i * 16 + a_r) * 128
                                                + kk * 32 + a_kb);
                LDSM_X4(ah[i][0], ah[i][1], ah[i][2], ah[i][3], sAh + SWZ(off));
                LDSM_X4(al[i][0], al[i][1], al[i][2], al[i][3], sAl + SWZ(off));
            }
            uint32_t b[4][2];
            #pragma unroll
            for (int jp = 0; jp < 2; jp++) {
                const uint32_t off = (uint32_t)((wn * 32 + jp * 16 + b_n) * 128
                                                + kk * 32 + b_kb);
                uint32_t r0, r1, r2, r3;
                LDSM_X4(r0, r1, r2, r3, sB + SWZ(off));
                b[jp * 2][0] = r0;     b[jp * 2][1] = r1;
                b[jp * 2 + 1][0] = r2; b[jp * 2 + 1][1] = r3;
            }
            #pragma unroll
            for (int i = 0; i < 2; i++)
                #pragma unroll
                for (int j = 0; j < 4; j++) {
                    IMMA_16832(acc_h[i][j], ah[i], b[j]);
                    IMMA_16832(acc_l[i][j], al[i], b[j]);
                }
        }
        __syncthreads();
    }

    // Epilogue: out = s_row * (acc_h + acc_l/128) + bias
    const int er = lane >> 2;
    const int ec = (lane & 3) * 2;
    #pragma unroll
    for (int i = 0; i < 2; i++) {
        const int row0 = m0 + wm * 32 + i * 16 + er;
        const float s0 = __ldg(&g_xs[row0]);
        const float s1 = __ldg(&g_xs[row0 + 8]);
        #pragma unroll
        for (int j = 0; j < 4; j++) {
            const int col = n0 + wn * 32 + j * 8 + ec;
            const float b0 = __ldg(bias + col);
            const float b1 = __ldg(bias + col + 1);
            float2 v0, v1;
            v0.x = s0 * ((float)acc_h[i][j][0] + (float)acc_l[i][j][0] * 0.0078125f) + b0;
            v0.y = s0 * ((float)acc_h[i][j][1] + (float)acc_l[i][j][1] * 0.0078125f) + b1;
            v1.x = s1 * ((float)acc_h[i][j][2] + (float)acc_l[i][j][2] * 0.0078125f) + b0;
            v1.y = s1 * ((float)acc_h[i][j][3] + (float)acc_l[i][j][3] * 0.0078125f) + b1;
            *reinterpret_cast<float2*>(out + (size_t)row0 * NDIM + col)       = v0;
            *reinterpret_cast<float2*>(out + (size_t)(row0 + 8) * NDIM + col) = v1;
        }
    }
}

// ---------------------------------------------------------------------------
// Launch
// ---------------------------------------------------------------------------
extern "C" void kernel_launch(void* const* d_in, const int* in_sizes, int n_in,
                              void* d_out, int out_size) {
    const float* x    = (const float*)d_in[0];   // [4,2048,4096]
    const float* w    = (const float*)d_in[1];   // [4096,4096]
    const float* bias = (const float*)d_in[2];   // [4096]
    float* out = (float*)d_out;                  // [4,2048,4096]

    reduce_gamma_kernel<<<1024, 256>>>(w);
    quant_fused_kernel<<<MDIM + 4096, 256>>>(x, w);

    cudaFuncSetAttribute(bitlinear_gemm_kernel,
                         cudaFuncAttributeMaxDynamicSharedMemorySize, SMEM_BYTES);
    bitlinear_gemm_kernel<<<dim3(NDIM / BN, MDIM / BM), 256, SMEM_BYTES>>>(bias, out);
}

// round 5
// speedup vs baseline: 5.1286x; 5.1286x over previous
#include <cuda_runtime.h>
#include <cuda_fp16.h>
#include <cstdint>

// ---------------------------------------------------------------------------
// BitLinear: out = x @ ternary(w)^T + bias
// x: [8192,4096] f32, w: [4096,4096] f32, bias: [4096] f32, out f32.
//
// Established over R3/R4: sm_103 legacy tensor pipe runs HMMA.16816.f32 at
// one per 16 cyc/SMSP (280 TF/s ceiling; int8 IMMA is 2x slower). The fp16
// mma.sync GEMM below measured ~980us = ~100% of that ceiling. This round
// keeps the GEMM and minimizes prepass: fused (w-absum + x->fp16 convert)
// kernel with float partial sums (fp64 only in the reduction tree), then a
// w-quant kernel, then the GEMM. 3 launches total.
// ---------------------------------------------------------------------------

#define MDIM 8192
#define NDIM 4096
#define KDIM 4096

#define BM 128
#define BN 128
#define BK 64
#define STAGES 3
#define KT (KDIM / BK)   // 64

// Scratch (device globals: allocation-free per harness rules)
__device__ double   g_partials[2048];
__device__ unsigned g_count = 0;
__device__ float    g_gamma_inv;
__device__ __align__(128) __half g_xq[(size_t)MDIM * KDIM];   // 64 MB
__device__ __align__(128) __half g_wq[(size_t)NDIM * KDIM];   // 32 MB

// ---------------------------------------------------------------------------
// Helpers
// ---------------------------------------------------------------------------
static __device__ __forceinline__ uint32_t smem_u32(const void* p) {
    uint32_t a;
    asm("{ .reg .u64 t; cvta.to.shared.u64 t, %1; cvt.u32.u64 %0, t; }"
        : "=r"(a) : "l"(p));
    return a;
}

static __device__ __forceinline__ void cp_async16(uint32_t s, const void* g) {
    asm volatile("cp.async.cg.shared.global [%0], [%1], 16;" :: "r"(s), "l"(g));
}

// SW128-style xor swizzle on byte offsets within 128B rows
#define SWZ(o) ((o) ^ (((o) >> 3) & 0x70))

#define LDSM_X4(r0, r1, r2, r3, addr)                                          \
    asm volatile("ldmatrix.sync.aligned.m8n8.x4.shared.b16 {%0,%1,%2,%3}, [%4];"\
                 : "=r"(r0), "=r"(r1), "=r"(r2), "=r"(r3) : "r"(addr))

#define LDSM_X2(r0, r1, addr)                                                  \
    asm volatile("ldmatrix.sync.aligned.m8n8.x2.shared.b16 {%0,%1}, [%2];"     \
                 : "=r"(r0), "=r"(r1) : "r"(addr))

#define MMA_16816(c, a, b)                                                     \
    asm volatile(                                                              \
        "mma.sync.aligned.m16n8k16.row.col.f32.f16.f16.f32 "                   \
        "{%0,%1,%2,%3}, {%4,%5,%6,%7}, {%8,%9}, {%0,%1,%2,%3};"                \
        : "+f"((c)[0]), "+f"((c)[1]), "+f"((c)[2]), "+f"((c)[3])               \
        : "r"((a)[0]), "r"((a)[1]), "r"((a)[2]), "r"((a)[3]),                  \
          "r"((b)[0]), "r"((b)[1]))

// ---------------------------------------------------------------------------
// Launch 1: fused (a) w-absum partial -> grid reduction -> g_gamma_inv,
//           (b) x -> fp16 convert (gamma-independent; overlaps in-kernel).
// 2048 blocks x 256 threads.
// ---------------------------------------------------------------------------
#define PRE_GRID 2048

__global__ __launch_bounds__(256)
void prepass_a_kernel(const float* __restrict__ w, const float* __restrict__ x) {
    __shared__ double sred[256];
    __shared__ bool is_last;
    const int tid = threadIdx.x;
    const int gtid = blockIdx.x * 256 + tid;
    const int gstride = PRE_GRID * 256;

    // ---- (a) |w| partial sums: 4 independent float accumulators for MLP ----
    {
        const float4* w4 = reinterpret_cast<const float4*>(w);
        const int n4 = (NDIM * KDIM) / 4;          // 4,194,304
        // n4 / gstride = 8 exactly -> each thread reads 8 float4, 2 per accum
        float s0 = 0.f, s1 = 0.f, s2 = 0.f, s3 = 0.f;
        #pragma unroll
        for (int it = 0; it < 2; it++) {
            const int base = gtid + it * 4 * gstride;
            float4 a = w4[base];
            float4 b = w4[base + gstride];
            float4 c = w4[base + 2 * gstride];
            float4 d = w4[base + 3 * gstride];
            s0 += fabsf(a.x) + fabsf(a.y) + fabsf(a.z) + fabsf(a.w);
            s1 += fabsf(b.x) + fabsf(b.y) + fabsf(b.z) + fabsf(b.w);
            s2 += fabsf(c.x) + fabsf(c.y) + fabsf(c.z) + fabsf(c.w);
            s3 += fabsf(d.x) + fabsf(d.y) + fabsf(d.z) + fabsf(d.w);
        }
        sred[tid] = (double)((s0 + s1) + (s2 + s3));
    }
    __syncthreads();
    for (int o = 128; o > 0; o >>= 1) {
        if (tid < o) sred[tid] += sred[tid + o];
        __syncthreads();
    }
    if (tid == 0) {
        g_partials[blockIdx.x] = sred[0];
        __threadfence();
        unsigned c = atomicAdd(&g_count, 1u);
        is_last = (c == PRE_GRID - 1);
    }

    // ---- (b) x -> fp16 convert (independent of gamma) ----
    {
        const float4* x4 = reinterpret_cast<const float4*>(x);
        uint2* q = reinterpret_cast<uint2*>(g_xq);
        const int n4 = (MDIM * KDIM) / 4;          // 8,388,608 = 16 per thread
        #pragma unroll 4
        for (int i = gtid; i < n4; i += gstride) {
            float4 v = x4[i];
            __half2 h0 = __floats2half2_rn(v.x, v.y);
            __half2 h1 = __floats2half2_rn(v.z, v.w);
            uint2 u;
            u.x = *reinterpret_cast<unsigned*>(&h0);
            u.y = *reinterpret_cast<unsigned*>(&h1);
            q[i] = u;
        }
    }

    // ---- finalize gamma (last block) ----
    __syncthreads();
    if (is_last) {
        double t = 0.0;
        for (int i = tid; i < PRE_GRID; i += 256) t += __ldcg(&g_partials[i]);
        sred[tid] = t;
        __syncthreads();
        for (int o = 128; o > 0; o >>= 1) {
            if (tid < o) sred[tid] += sred[tid + o];
            __syncthreads();
        }
        if (tid == 0) {
            double g = sred[0] / (double)((size_t)NDIM * KDIM);
            if (g < 1e-8) g = 1e-8;
            g_gamma_inv = (float)(1.0 / g);
            g_count = 0;   // reset for next graph replay
        }
    }
}

// ---------------------------------------------------------------------------
// Launch 2: w -> ternary fp16 (needs gamma)
// ---------------------------------------------------------------------------
__global__ __launch_bounds__(256)
void prepass_b_kernel(const float* __restrict__ w) {
    const float ginv = g_gamma_inv;
    const float4* w4 = reinterpret_cast<const float4*>(w);
    uint2* q = reinterpret_cast<uint2*>(g_wq);
    const int n4 = (NDIM * KDIM) / 4;
    const int gstride = gridDim.x * blockDim.x;
    #pragma unroll 4
    for (int i = blockIdx.x * blockDim.x + threadIdx.x; i < n4; i += gstride) {
        float4 v = w4[i];
        float a = fminf(1.f, fmaxf(-1.f, rintf(v.x * ginv)));
        float b = fminf(1.f, fmaxf(-1.f, rintf(v.y * ginv)));
        float c = fminf(1.f, fmaxf(-1.f, rintf(v.z * ginv)));
        float d = fminf(1.f, fmaxf(-1.f, rintf(v.w * ginv)));
        __half2 h0 = __floats2half2_rn(a, b);
        __half2 h1 = __floats2half2_rn(c, d);
        uint2 u;
        u.x = *reinterpret_cast<unsigned*>(&h0);
        u.y = *reinterpret_cast<unsigned*>(&h1);
        q[i] = u;
    }
}

// ---------------------------------------------------------------------------
// Launch 3: GEMM. 128x128 CTA tile, BK=64, 3-stage cp.async, mma.sync 16816.
// (Unchanged from the 1071us round: measured at the legacy HMMA ceiling.)
// ---------------------------------------------------------------------------
static constexpr int STAGE_BYTES = BM * BK * 2;               // 16384
static constexpr int SMEM_BYTES  = 2 * STAGES * STAGE_BYTES;  // 98304

__global__ __launch_bounds__(256, 2)
void bitlinear_gemm_kernel(const float* __restrict__ bias, float* __restrict__ out) {
    extern __shared__ __align__(128) char smem_raw[];
    const uint32_t sbase = smem_u32(smem_raw);
    const uint32_t sBb   = sbase + STAGES * STAGE_BYTES;

    const int tid    = threadIdx.x;
    const int wid    = tid >> 5;
    const int lane   = tid & 31;
    const int warp_m = wid & 1;        // 0..1 -> 64 rows each
    const int warp_n = wid >> 1;       // 0..3 -> 32 cols each
    const int m0 = blockIdx.y * BM;
    const int n0 = blockIdx.x * BN;

    const __half* Ag = g_xq + (size_t)m0 * KDIM;
    const __half* Bg = g_wq + (size_t)n0 * KDIM;

    const int lrow0 = tid >> 3;        // rows tid>>3 + {0,32,64,96}
    const int lkc   = tid & 7;

    float acc[4][4][4];
    #pragma unroll
    for (int i = 0; i < 4; i++)
        #pragma unroll
        for (int j = 0; j < 4; j++)
            #pragma unroll
            for (int r = 0; r < 4; r++) acc[i][j][r] = 0.f;

    auto load_stage = [&](int kt) {
        const int s = kt % STAGES;
        const uint32_t sA = sbase + s * STAGE_BYTES;
        const uint32_t sB = sBb   + s * STAGE_BYTES;
        const __half* Akt = Ag + kt * BK;
        const __half* Bkt = Bg + kt * BK;
        #pragma unroll
        for (int i = 0; i < 4; i++) {
            const int r = lrow0 + i * 32;
            const uint32_t d = SWZ((uint32_t)(r * 128 + lkc * 16));
            cp_async16(sA + d, Akt + (size_t)r * KDIM + lkc * 8);
            cp_async16(sB + d, Bkt + (size_t)r * KDIM + lkc * 8);
        }
    };

    load_stage(0);
    asm volatile("cp.async.commit_group;" ::: "memory");
    load_stage(1);
    asm volatile("cp.async.commit_group;" ::: "memory");

    const int a_row  = warp_m * 64 + (lane & 15);
    const int a_cchk = (lane >> 4);          // 0/1
    const int b_row  = warp_n * 32 + (lane & 7);
    const int b_cchk = (lane >> 3) & 1;      // 0/1

    for (int kt = 0; kt < KT; ++kt) {
        asm volatile("cp.async.wait_group 1;" ::: "memory");
        __syncthreads();

        const int ktn = kt + (STAGES - 1);
        if (ktn < KT) load_stage(ktn);
        asm volatile("cp.async.commit_group;" ::: "memory");

        const int s = kt % STAGES;
        const uint32_t sA = sbase + s * STAGE_BYTES;
        const uint32_t sB = sBb   + s * STAGE_BYTES;

        #pragma unroll
        for (int kk = 0; kk < 4; kk++) {
            uint32_t a[4][4];
            #pragma unroll
            for (int i = 0; i < 4; i++) {
                const uint32_t off = (uint32_t)((a_row + i * 16) * 128
                                                + kk * 32 + a_cchk * 16);
                LDSM_X4(a[i][0], a[i][1], a[i][2], a[i][3], sA + SWZ(off));
            }
            uint32_t b[4][2];
            #pragma unroll
            for (int j = 0; j < 4; j++) {
                const uint32_t off = (uint32_t)((b_row + j * 8) * 128
                                                + kk * 32 + b_cchk * 16);
                LDSM_X2(b[j][0], b[j][1], sB + SWZ(off));
            }
            #pragma unroll
            for (int i = 0; i < 4; i++)
                #pragma unroll
                for (int j = 0; j < 4; j++)
                    MMA_16816(acc[i][j], a[i], b[j]);
        }
    }

    // Epilogue
    const int er = lane >> 2;
    const int ec = (lane & 3) * 2;
    float bb[4][2];
    #pragma unroll
    for (int j = 0; j < 4; j++) {
        const int col = n0 + warp_n * 32 + j * 8 + ec;
        bb[j][0] = __ldg(bias + col);
        bb[j][1] = __ldg(bias + col + 1);
    }
    #pragma unroll
    for (int i = 0; i < 4; i++) {
        const int row = m0 + warp_m * 64 + i * 16 + er;
        #pragma unroll
        for (int j = 0; j < 4; j++) {
            const int col = n0 + warp_n * 32 + j * 8 + ec;
            float2 v0 = make_float2(acc[i][j][0] + bb[j][0],
                                    acc[i][j][1] + bb[j][1]);
            float2 v1 = make_float2(acc[i][j][2] + bb[j][0],
                                    acc[i][j][3] + bb[j][1]);
            *reinterpret_cast<float2*>(out + (size_t)row * NDIM + col)       = v0;
            *reinterpret_cast<float2*>(out + (size_t)(row + 8) * NDIM + col) = v1;
        }
    }
}

// ---------------------------------------------------------------------------
// Launch
// ---------------------------------------------------------------------------
extern "C" void kernel_launch(void* const* d_in, const int* in_sizes, int n_in,
                              void* d_out, int out_size) {
    const float* x    = (const float*)d_in[0];   // [4,2048,4096]
    const float* w    = (const float*)d_in[1];   // [4096,4096]
    const float* bias = (const float*)d_in[2];   // [4096]
    float* out = (float*)d_out;                  // [4,2048,4096]

    prepass_a_kernel<<<PRE_GRID, 256>>>(w, x);
    prepass_b_kernel<<<2048, 256>>>(w);

    cudaFuncSetAttribute(bitlinear_gemm_kernel,
                         cudaFuncAttributeMaxDynamicSharedMemorySize, SMEM_BYTES);
    bitlinear_gemm_kernel<<<dim3(NDIM / BN, MDIM / BM), 256, SMEM_BYTES>>>(bias, out);
}

// round 6
// speedup vs baseline: 5.2023x; 1.0144x over previous
#include <cuda_runtime.h>
#include <cuda_fp16.h>
#include <cstdint>

// ---------------------------------------------------------------------------
// BitLinear: out = x @ ternary(w)^T + bias
// x: [8192,4096] f32, w: [4096,4096] f32, bias: [4096] f32, out f32.
//
// R5 measured: fp16 mma.sync GEMM (128x128 tile) at 637us = 432 TF/s, with an
// L2-traffic floor of ~354us at that tile shape. This round: 256x128 CTA tile
// (L2 traffic 4.3GB -> 3.2GB), 512 threads, 4-stage cp.async, 1 CTA/SM.
// Prepass: fused (w-absum + x->fp16) then w-quant. 3 launches total.
// ---------------------------------------------------------------------------

#define MDIM 8192
#define NDIM 4096
#define KDIM 4096

#define BM 256
#define BN 128
#define BK 64
#define STAGES 4
#define KT (KDIM / BK)   // 64

// Scratch (device globals: allocation-free per harness rules)
__device__ double   g_partials[2048];
__device__ unsigned g_count = 0;
__device__ float    g_gamma_inv;
__device__ __align__(128) __half g_xq[(size_t)MDIM * KDIM];   // 64 MB
__device__ __align__(128) __half g_wq[(size_t)NDIM * KDIM];   // 32 MB

// ---------------------------------------------------------------------------
// Helpers
// ---------------------------------------------------------------------------
static __device__ __forceinline__ uint32_t smem_u32(const void* p) {
    uint32_t a;
    asm("{ .reg .u64 t; cvta.to.shared.u64 t, %1; cvt.u32.u64 %0, t; }"
        : "=r"(a) : "l"(p));
    return a;
}

static __device__ __forceinline__ void cp_async16(uint32_t s, const void* g) {
    asm volatile("cp.async.cg.shared.global [%0], [%1], 16;" :: "r"(s), "l"(g));
}

// SW128-style xor swizzle on byte offsets within 128B rows
#define SWZ(o) ((o) ^ (((o) >> 3) & 0x70))

#define LDSM_X4(r0, r1, r2, r3, addr)                                          \
    asm volatile("ldmatrix.sync.aligned.m8n8.x4.shared.b16 {%0,%1,%2,%3}, [%4];"\
                 : "=r"(r0), "=r"(r1), "=r"(r2), "=r"(r3) : "r"(addr))

#define MMA_16816(c, a, b)                                                     \
    asm volatile(                                                              \
        "mma.sync.aligned.m16n8k16.row.col.f32.f16.f16.f32 "                   \
        "{%0,%1,%2,%3}, {%4,%5,%6,%7}, {%8,%9}, {%0,%1,%2,%3};"                \
        : "+f"((c)[0]), "+f"((c)[1]), "+f"((c)[2]), "+f"((c)[3])               \
        : "r"((a)[0]), "r"((a)[1]), "r"((a)[2]), "r"((a)[3]),                  \
          "r"((b)[0]), "r"((b)[1]))

// ---------------------------------------------------------------------------
// Launch 1: fused (a) w-absum -> grid reduction -> g_gamma_inv,
//           (b) x -> fp16 convert (gamma-independent).
// ---------------------------------------------------------------------------
#define PRE_GRID 2048

__global__ __launch_bounds__(256)
void prepass_a_kernel(const float* __restrict__ w, const float* __restrict__ x) {
    __shared__ double sred[256];
    __shared__ bool is_last;
    const int tid = threadIdx.x;
    const int gtid = blockIdx.x * 256 + tid;
    const int gstride = PRE_GRID * 256;

    // ---- (a) |w| partial sums: 4 independent float accumulators ----
    {
        const float4* w4 = reinterpret_cast<const float4*>(w);
        float s0 = 0.f, s1 = 0.f, s2 = 0.f, s3 = 0.f;
        #pragma unroll
        for (int it = 0; it < 2; it++) {
            const int base = gtid + it * 4 * gstride;
            float4 a = w4[base];
            float4 b = w4[base + gstride];
            float4 c = w4[base + 2 * gstride];
            float4 d = w4[base + 3 * gstride];
            s0 += fabsf(a.x) + fabsf(a.y) + fabsf(a.z) + fabsf(a.w);
            s1 += fabsf(b.x) + fabsf(b.y) + fabsf(b.z) + fabsf(b.w);
            s2 += fabsf(c.x) + fabsf(c.y) + fabsf(c.z) + fabsf(c.w);
            s3 += fabsf(d.x) + fabsf(d.y) + fabsf(d.z) + fabsf(d.w);
        }
        sred[tid] = (double)((s0 + s1) + (s2 + s3));
    }
    __syncthreads();
    for (int o = 128; o > 0; o >>= 1) {
        if (tid < o) sred[tid] += sred[tid + o];
        __syncthreads();
    }
    if (tid == 0) {
        g_partials[blockIdx.x] = sred[0];
        __threadfence();
        unsigned c = atomicAdd(&g_count, 1u);
        is_last = (c == PRE_GRID - 1);
    }

    // ---- (b) x -> fp16 convert ----
    {
        const float4* x4 = reinterpret_cast<const float4*>(x);
        uint2* q = reinterpret_cast<uint2*>(g_xq);
        const int n4 = (MDIM * KDIM) / 4;
        #pragma unroll 4
        for (int i = gtid; i < n4; i += gstride) {
            float4 v = x4[i];
            __half2 h0 = __floats2half2_rn(v.x, v.y);
            __half2 h1 = __floats2half2_rn(v.z, v.w);
            uint2 u;
            u.x = *reinterpret_cast<unsigned*>(&h0);
            u.y = *reinterpret_cast<unsigned*>(&h1);
            q[i] = u;
        }
    }

    // ---- finalize gamma (last block) ----
    __syncthreads();
    if (is_last) {
        double t = 0.0;
        for (int i = tid; i < PRE_GRID; i += 256) t += __ldcg(&g_partials[i]);
        sred[tid] = t;
        __syncthreads();
        for (int o = 128; o > 0; o >>= 1) {
            if (tid < o) sred[tid] += sred[tid + o];
            __syncthreads();
        }
        if (tid == 0) {
            double g = sred[0] / (double)((size_t)NDIM * KDIM);
            if (g < 1e-8) g = 1e-8;
            g_gamma_inv = (float)(1.0 / g);
            g_count = 0;   // reset for next graph replay
        }
    }
}

// ---------------------------------------------------------------------------
// Launch 2: w -> ternary fp16 (needs gamma)
// ---------------------------------------------------------------------------
__global__ __launch_bounds__(256)
void prepass_b_kernel(const float* __restrict__ w) {
    const float ginv = g_gamma_inv;
    const float4* w4 = reinterpret_cast<const float4*>(w);
    uint2* q = reinterpret_cast<uint2*>(g_wq);
    const int n4 = (NDIM * KDIM) / 4;
    const int gstride = gridDim.x * blockDim.x;
    #pragma unroll 4
    for (int i = blockIdx.x * blockDim.x + threadIdx.x; i < n4; i += gstride) {
        float4 v = w4[i];
        float a = fminf(1.f, fmaxf(-1.f, rintf(v.x * ginv)));
        float b = fminf(1.f, fmaxf(-1.f, rintf(v.y * ginv)));
        float c = fminf(1.f, fmaxf(-1.f, rintf(v.z * ginv)));
        float d = fminf(1.f, fmaxf(-1.f, rintf(v.w * ginv)));
        __half2 h0 = __floats2half2_rn(a, b);
        __half2 h1 = __floats2half2_rn(c, d);
        uint2 u;
        u.x = *reinterpret_cast<unsigned*>(&h0);
        u.y = *reinterpret_cast<unsigned*>(&h1);
        q[i] = u;
    }
}

// ---------------------------------------------------------------------------
// Launch 3: GEMM. 256(M) x 128(N) CTA tile, BK=64, 4-stage cp.async,
// 512 threads (16 warps: wm = wid&7 -> 32 rows, wn = wid>>3 -> 64 cols).
// Warp tile 32x64: acc[2][8][4]. A stages then B stages in SMEM.
// ---------------------------------------------------------------------------
static constexpr int A_STAGE = BM * BK * 2;                   // 32768
static constexpr int B_STAGE = BN * BK * 2;                   // 16384
static constexpr int STAGE_BYTES = A_STAGE + B_STAGE;         // 49152
static constexpr int SMEM_BYTES  = STAGES * STAGE_BYTES;      // 196608

__global__ __launch_bounds__(512, 1)
void bitlinear_gemm_kernel(const float* __restrict__ bias, float* __restrict__ out) {
    extern __shared__ __align__(128) char smem_raw[];
    const uint32_t sbase = smem_u32(smem_raw);

    const int tid  = threadIdx.x;
    const int wid  = tid >> 5;
    const int lane = tid & 31;
    const int wm = wid & 7;        // 0..7 -> 32 rows each
    const int wn = wid >> 3;       // 0..1 -> 64 cols each
    const int m0 = blockIdx.y * BM;
    const int n0 = blockIdx.x * BN;

    const __half* Ag = g_xq + (size_t)m0 * KDIM;
    const __half* Bg = g_wq + (size_t)n0 * KDIM;

    // Load mapping: A tile 2048 16B-chunks, B tile 1024 chunks; 512 threads.
    const int lrow = tid >> 3;     // 0..63
    const int lkc  = tid & 7;

    float acc[2][8][4];
    #pragma unroll
    for (int i = 0; i < 2; i++)
        #pragma unroll
        for (int j = 0; j < 8; j++)
            #pragma unroll
            for (int r = 0; r < 4; r++) acc[i][j][r] = 0.f;

    auto load_stage = [&](int kt) {
        const int s = kt & (STAGES - 1);
        const uint32_t sA = sbase + s * STAGE_BYTES;
        const uint32_t sB = sA + A_STAGE;
        const __half* Akt = Ag + kt * BK;
        const __half* Bkt = Bg + kt * BK;
        #pragma unroll
        for (int i = 0; i < 4; i++) {
            const int r = lrow + i * 64;
            const uint32_t d = SWZ((uint32_t)(r * 128 + lkc * 16));
            cp_async16(sA + d, Akt + (size_t)r * KDIM + lkc * 8);
        }
        #pragma unroll
        for (int i = 0; i < 2; i++) {
            const int r = lrow + i * 64;
            const uint32_t d = SWZ((uint32_t)(r * 128 + lkc * 16));
            cp_async16(sB + d, Bkt + (size_t)r * KDIM + lkc * 8);
        }
    };

    load_stage(0);
    asm volatile("cp.async.commit_group;" ::: "memory");
    load_stage(1);
    asm volatile("cp.async.commit_group;" ::: "memory");
    load_stage(2);
    asm volatile("cp.async.commit_group;" ::: "memory");

    // ldmatrix lane addressing
    const int a_r  = lane & 15;                          // row within m16
    const int a_ck = (lane >> 4) * 16;                   // k-byte half
    const int b_n  = ((lane >> 4) & 1) * 8 + (lane & 7); // n row within n16 pair
    const int b_ck = ((lane >> 3) & 1) * 16;             // k-byte half

    for (int kt = 0; kt < KT; ++kt) {
        asm volatile("cp.async.wait_group %0;" :: "n"(STAGES - 2) : "memory");
        __syncthreads();

        const int ktn = kt + (STAGES - 1);
        if (ktn < KT) load_stage(ktn);
        asm volatile("cp.async.commit_group;" ::: "memory");

        const int s = kt & (STAGES - 1);
        const uint32_t sA = sbase + s * STAGE_BYTES;
        const uint32_t sB = sA + A_STAGE;

        #pragma unroll
        for (int kk = 0; kk < 4; kk++) {
            uint32_t a[2][4];
            #pragma unroll
            for (int i = 0; i < 2; i++) {
                const uint32_t off = (uint32_t)((wm * 32 + i * 16 + a_r) * 128
                                                + kk * 32 + a_ck);
                LDSM_X4(a[i][0], a[i][1], a[i][2], a[i][3], sA + SWZ(off));
            }
            uint32_t b[8][2];
            #pragma unroll
            for (int jp = 0; jp < 4; jp++) {
                const uint32_t off = (uint32_t)((wn * 64 + jp * 16 + b_n) * 128
                                                + kk * 32 + b_ck);
                uint32_t r0, r1, r2, r3;
                LDSM_X4(r0, r1, r2, r3, sB + SWZ(off));
                b[jp * 2][0] = r0;     b[jp * 2][1] = r1;
                b[jp * 2 + 1][0] = r2; b[jp * 2 + 1][1] = r3;
            }
            #pragma unroll
            for (int i = 0; i < 2; i++)
                #pragma unroll
                for (int j = 0; j < 8; j++)
                    MMA_16816(acc[i][j], a[i], b[j]);
        }
        __syncthreads();
    }

    // Epilogue
    const int er = lane >> 2;
    const int ec = (lane & 3) * 2;
    float bb[8][2];
    #pragma unroll
    for (int j = 0; j < 8; j++) {
        const int col = n0 + wn * 64 + j * 8 + ec;
        bb[j][0] = __ldg(bias + col);
        bb[j][1] = __ldg(bias + col + 1);
    }
    #pragma unroll
    for (int i = 0; i < 2; i++) {
        const int row = m0 + wm * 32 + i * 16 + er;
        #pragma unroll
        for (int j = 0; j < 8; j++) {
            const int col = n0 + wn * 64 + j * 8 + ec;
            float2 v0 = make_float2(acc[i][j][0] + bb[j][0],
                                    acc[i][j][1] + bb[j][1]);
            float2 v1 = make_float2(acc[i][j][2] + bb[j][0],
                                    acc[i][j][3] + bb[j][1]);
            *reinterpret_cast<float2*>(out + (size_t)row * NDIM + col)       = v0;
            *reinterpret_cast<float2*>(out + (size_t)(row + 8) * NDIM + col) = v1;
        }
    }
}

// ---------------------------------------------------------------------------
// Launch
// ---------------------------------------------------------------------------
extern "C" void kernel_launch(void* const* d_in, const int* in_sizes, int n_in,
                              void* d_out, int out_size) {
    const float* x    = (const float*)d_in[0];   // [4,2048,4096]
    const float* w    = (const float*)d_in[1];   // [4096,4096]
    const float* bias = (const float*)d_in[2];   // [4096]
    float* out = (float*)d_out;                  // [4,2048,4096]

    prepass_a_kernel<<<PRE_GRID, 256>>>(w, x);
    prepass_b_kernel<<<2048, 256>>>(w);

    cudaFuncSetAttribute(bitlinear_gemm_kernel,
                         cudaFuncAttributeMaxDynamicSharedMemorySize, SMEM_BYTES);
    bitlinear_gemm_kernel<<<dim3(NDIM / BN, MDIM / BM), 512, SMEM_BYTES>>>(bias, out);
}